// round 14
// baseline (speedup 1.0000x reference)
#include <cuda_runtime.h>
#include <math.h>
#include <stdint.h>

// ---------------- dims ----------------
#define B_IMG 64
#define R_REG 36
#define E_DIM 1024
#define C_CAP 64
#define L_W   32
#define N_DEP 30
#define NBLK  32
#define BLK   32
#define HID   512
#define LAM   9.0f

typedef unsigned long long ull;

// f32x2 packed helpers (sm_100+ PTX)
#define PK2(d, lo, hi)   asm("mov.b64 %0, {%1, %2};" : "=l"(d) : "f"(lo), "f"(hi))
#define UPK2(lo, hi, s)  asm("mov.b64 {%0, %1}, %2;" : "=f"(lo), "=f"(hi) : "l"(s))
#define FFMA2(d, a, b, c) asm("fma.rn.f32x2 %0, %1, %2, %3;" : "=l"(d) : "l"(a), "l"(b), "l"(c))
#define FADD2(d, a, b)    asm("add.rn.f32x2 %0, %1, %2;" : "=l"(d) : "l"(a), "l"(b))
#define TANH_APX(d, a)    asm("tanh.approx.f32 %0, %1;" : "=f"(d) : "f"(a))

// ---------------- scratch ----------------
__device__ float g_attn[(size_t)B_IMG * R_REG * C_CAP * L_W];
__device__ float g_scap[C_CAP * L_W];
__device__ float g_qns[C_CAP * L_W * NBLK];
__device__ float g_x[(size_t)C_CAP * B_IMG * L_W * NBLK];
__device__ float g_w[B_IMG * C_CAP];
__device__ float2 g_Wmp[(NBLK / 2) * HID];      // [k-pair][h] -> (wmu[2j], wmu[2j+1])
__device__ float2 g_Wlp[(NBLK / 2) * HID];      // [k-pair][h] -> (wlv[2j], wlv[2j+1])
__device__ float2 g_W1p[(NBLK / 2) * HID];      // [k-pair][h] -> (w1[2j], w1[2j+1])

// ---------------- compose W @ W_gc ----------------
__global__ void k_compose(const float* __restrict__ Wgc,
                          const float* __restrict__ Wmu,
                          const float* __restrict__ Wlv,
                          const float* __restrict__ W1) {
    int h = blockIdx.x;
    int m = blockIdx.y;
    int k = threadIdx.x;  // 0..31
    const float* W = (m == 0) ? Wmu : (m == 1) ? Wlv : W1;
    float acc = 0.f;
    #pragma unroll 8
    for (int j = 0; j < HID; j++)
        acc += W[h * HID + j] * Wgc[j * NBLK + k];
    float2* dst = (m == 0) ? g_Wmp : (m == 1) ? g_Wlp : g_W1p;
    if (k & 1) dst[(k >> 1) * HID + h].y = acc;
    else       dst[(k >> 1) * HID + h].x = acc;
}

// ---------------- kernel A: per-caption s[l] + block norms (R13 proven form) ----------------
#define A_SMEM_FLOATS (32 * 1025 + 1024 + 1024)
__global__ void k_caption(const float* __restrict__ caps,
                          const int* __restrict__ deps) {
    int c = blockIdx.x;
    int t = threadIdx.x;  // 256
    extern __shared__ float sh[];
    float* cs  = sh;                  // [32][1025]
    float* G   = cs + 32 * 1025;
    float* adj = G + 1024;

    const float* cp = caps + (size_t)c * L_W * E_DIM;
    for (int i = t; i < L_W * E_DIM; i += 256) {
        int l = i >> 10, e = i & 1023;
        cs[l * 1025 + e] = cp[i];
    }
    __syncthreads();

    for (int p = t; p < 1024; p += 256) {
        int l = p >> 5, k = p & 31;
        float s = 0.f;
        #pragma unroll
        for (int j = 0; j < 32; j++) {
            float v = cs[l * 1025 + k * 32 + j];
            s += v * v;
        }
        g_qns[c * 1024 + p] = sqrtf(s);
    }

    for (int p = t; p < 1024; p += 256) {
        int i = p >> 5, j = p & 31;
        float acc = 0.f;
        #pragma unroll 8
        for (int e = 0; e < E_DIM; e++)
            acc += cs[i * 1025 + e] * cs[j * 1025 + e];
        G[p] = acc;
    }
    __syncthreads();

    if (t < 32) {
        float m = -1e30f;
        for (int j = 0; j < 32; j++) m = fmaxf(m, G[t * 32 + j]);
        float s = 0.f;
        for (int j = 0; j < 32; j++) {
            float e = __expf(LAM * (G[t * 32 + j] - m));
            G[t * 32 + j] = e;
            s += e;
        }
        float inv = 1.f / s;
        for (int j = 0; j < 32; j++) G[t * 32 + j] *= inv;
    }
    for (int p = t; p < 1024; p += 256) adj[p] = 0.f;
    __syncthreads();
    if (t == 0) {
        for (int i = 1; i < N_DEP; i++) {
            int a = deps[c * (N_DEP * 2) + i * 2 + 0];
            int b = deps[c * (N_DEP * 2) + i * 2 + 1];
            adj[a * 32 + b] = 1.f;
            adj[b * 32 + a] = 1.f;
        }
        for (int i = 0; i < 32; i++) adj[i * 32 + i] += 1.f;
    }
    __syncthreads();
    if (t < 32) {
        float ss = 0.f;
        for (int j = 0; j < 32; j++) {
            float m2 = adj[t * 32 + j] * G[t * 32 + j];
            ss += m2 * m2;
        }
        float inv = 1.f / (sqrtf(ss) + 1e-8f);
        float s = 0.f;
        for (int j = 0; j < 32; j++) {
            float a = adj[t * 32 + j];
            s += a * G[t * 32 + j] * inv * a;
        }
        g_scap[c * 32 + t] = s;
    }
}

// ---------------- kernel B: logits GEMM, 128x256 tile, one wave ----------------
__global__ void __launch_bounds__(512) k_gemm_nt(const float* __restrict__ A,
                                                 const float* __restrict__ B,
                                                 float* __restrict__ C) {
    __shared__ __align__(16) float As[2][8][132];
    __shared__ __align__(16) float Bs[2][8][260];
    int tm = blockIdx.y, tn = blockIdx.x;   // tm: 0..17, tn: 0..7
    int t = threadIdx.x;                    // 512
    int ty = t >> 5;                        // 0..15 (row group; constant per warp)
    int tx = t & 31;                        // 0..31 (col group)
    int lr = t >> 1;                        // 0..255 B load row; 0..127 A load row (t<256)
    int lk = (t & 1) * 4;
    const float* Bb = B + (size_t)(tn * 256 + lr) * E_DIM + lk;
    const float* Ab = A + (size_t)(tm * 128 + lr) * E_DIM + lk;  // only t<256
    ull acc[8][4];
    #pragma unroll
    for (int i = 0; i < 8; i++)
        #pragma unroll
        for (int j = 0; j < 4; j++) acc[i][j] = 0ULL;

    float4 bv = *(const float4*)(Bb);
    float4 av = make_float4(0.f, 0.f, 0.f, 0.f);
    if (t < 256) av = *(const float4*)(Ab);
    Bs[0][lk + 0][lr] = bv.x; Bs[0][lk + 1][lr] = bv.y;
    Bs[0][lk + 2][lr] = bv.z; Bs[0][lk + 3][lr] = bv.w;
    if (t < 256) {
        As[0][lk + 0][lr] = av.x; As[0][lk + 1][lr] = av.y;
        As[0][lk + 2][lr] = av.z; As[0][lk + 3][lr] = av.w;
    }
    __syncthreads();

    int p = 0;
    for (int k0 = 0; k0 < E_DIM; k0 += 8) {
        if (k0 + 8 < E_DIM) {
            bv = *(const float4*)(Bb + k0 + 8);
            if (t < 256) av = *(const float4*)(Ab + k0 + 8);
        }
        #pragma unroll
        for (int k = 0; k < 8; k++) {
            float4 a0 = *(const float4*)&As[p][k][ty * 4];
            float4 a1 = *(const float4*)&As[p][k][64 + ty * 4];
            ulonglong2 bq0 = *(const ulonglong2*)&Bs[p][k][tx * 4];
            ulonglong2 bq1 = *(const ulonglong2*)&Bs[p][k][128 + tx * 4];
            float a_[8] = {a0.x, a0.y, a0.z, a0.w, a1.x, a1.y, a1.z, a1.w};
            #pragma unroll
            for (int i = 0; i < 8; i++) {
                ull ai2; PK2(ai2, a_[i], a_[i]);
                FFMA2(acc[i][0], ai2, bq0.x, acc[i][0]);
                FFMA2(acc[i][1], ai2, bq0.y, acc[i][1]);
                FFMA2(acc[i][2], ai2, bq1.x, acc[i][2]);
                FFMA2(acc[i][3], ai2, bq1.y, acc[i][3]);
            }
        }
        if (k0 + 8 < E_DIM) {
            int q = p ^ 1;
            Bs[q][lk + 0][lr] = bv.x; Bs[q][lk + 1][lr] = bv.y;
            Bs[q][lk + 2][lr] = bv.z; Bs[q][lk + 3][lr] = bv.w;
            if (t < 256) {
                As[q][lk + 0][lr] = av.x; As[q][lk + 1][lr] = av.y;
                As[q][lk + 2][lr] = av.z; As[q][lk + 3][lr] = av.w;
            }
            __syncthreads();
            p = q;
        }
    }
    const int N = C_CAP * L_W;
    #pragma unroll
    for (int i = 0; i < 8; i++) {
        int row = tm * 128 + ((i < 4) ? (ty * 4 + i) : (64 + ty * 4 + (i - 4)));
        float c0, c1, c2, c3, c4, c5, c6, c7;
        UPK2(c0, c1, acc[i][0]); UPK2(c2, c3, acc[i][1]);
        UPK2(c4, c5, acc[i][2]); UPK2(c6, c7, acc[i][3]);
        *(float4*)(C + (size_t)row * N + tn * 256 + tx * 4) = make_float4(c0, c1, c2, c3);
        *(float4*)(C + (size_t)row * N + tn * 256 + 128 + tx * 4) = make_float4(c4, c5, c6, c7);
    }
}

// ---------------- kernel C: fused per-(c,b) (R13 proven form, UNCHANGED) ----------------
__global__ void __launch_bounds__(512) k_fused(const float* __restrict__ imgs,
                                               const float* __restrict__ caps,
                                               const float* __restrict__ b1,
                                               const float* __restrict__ W2,
                                               const float* __restrict__ b2,
                                               float* __restrict__ out_sim) {
    int c = blockIdx.x;
    int b = blockIdx.y;
    int t = threadIdx.x;  // 512 = 16 warps
    int warp = t >> 5, lane = t & 31;
    __shared__ __align__(16) float tnorm[L_W * 37];
    __shared__ __align__(16) float wlr[L_W * R_REG];  // [l][36]
    __shared__ __align__(16) float xs[L_W * NBLK];
    __shared__ __align__(16) float xn[L_W * NBLK];    // numerator partials
    __shared__ __align__(16) float xc[L_W * NBLK];    // wctx-norm^2 partials
    __shared__ float ssc[L_W];
    __shared__ __align__(16) float qsh[L_W * NBLK];
    __shared__ float red[16];

    for (int i = t; i < 1024; i += 512) qsh[i] = g_qns[c * 1024 + i];
    if (t < L_W) ssc[t] = g_scap[c * L_W + t];

    // phase 1 (coalesced): warp = region, lane = word
    #pragma unroll
    for (int p = 0; p < 3; p++) {
        int r = warp + p * 16;
        if (r < R_REG) {
            float a = g_attn[((size_t)(b * R_REG + r)) * (C_CAP * L_W) + c * L_W + lane];
            a = (a >= 0.f) ? a : 0.1f * a;
            float ss = a * a;
            #pragma unroll
            for (int o = 16; o; o >>= 1) ss += __shfl_xor_sync(0xffffffffu, ss, o);
            tnorm[lane * 37 + r] = a * (1.f / (sqrtf(ss) + 1e-8f));
        }
    }
    __syncthreads();
    // softmax over regions per word
    if (t < L_W) {
        float m = -1e30f;
        #pragma unroll
        for (int r = 0; r < R_REG; r++) m = fmaxf(m, tnorm[t * 37 + r]);
        float s = 0.f;
        float e[R_REG];
        #pragma unroll
        for (int r = 0; r < R_REG; r++) {
            e[r] = __expf(LAM * (tnorm[t * 37 + r] - m));
            s += e[r];
        }
        float inv = 1.f / s;
        #pragma unroll
        for (int r = 0; r < R_REG; r++) wlr[t * R_REG + r] = e[r] * inv;
    }
    __syncthreads();

    // phase 2+3: 16-lane group owns one block; lane gl owns elements gl, gl+16
    int group = lane >> 4;            // 0 or 1
    int gl = lane & 15;
    int kblk = warp + 16 * group;     // block index 0..31
    int ea = kblk * 32 + gl;
    int eb = ea + 16;
    const float* imgb = imgs + (size_t)b * R_REG * E_DIM;
    const float* capc = caps + (size_t)c * L_W * E_DIM;
    ull cpa[18], cpb[18];             // natural-r pairs (img[2i][e], img[2i+1][e])
    #pragma unroll
    for (int i = 0; i < 18; i++) {
        float va0 = imgb[(2 * i) * E_DIM + ea];
        float va1 = imgb[(2 * i + 1) * E_DIM + ea];
        PK2(cpa[i], va0, va1);
        float vb0 = imgb[(2 * i) * E_DIM + eb];
        float vb1 = imgb[(2 * i + 1) * E_DIM + eb];
        PK2(cpb[i], vb0, vb1);
    }
    bool hi8 = (gl & 8) != 0;
    #pragma unroll 1
    for (int l0 = 0; l0 < L_W; l0 += 4) {
        // prefetch the 4 q-pairs
        float qa[4], qb[4];
        #pragma unroll
        for (int u = 0; u < 4; u++) {
            qa[u] = capc[(l0 + u) * E_DIM + ea];
            qb[u] = capc[(l0 + u) * E_DIM + eb];
        }
        float vch[4];
        #pragma unroll
        for (int u = 0; u < 4; u++) {
            const ulonglong2* wp = (const ulonglong2*)(wlr + (l0 + u) * R_REG);
            ull aa0 = 0ULL, aa1 = 0ULL, ab0 = 0ULL, ab1 = 0ULL;
            #pragma unroll
            for (int i = 0; i < 9; i++) {
                ulonglong2 wq = wp[i];
                FFMA2(aa0, wq.x, cpa[2 * i + 0], aa0);
                FFMA2(aa1, wq.y, cpa[2 * i + 1], aa1);
                FFMA2(ab0, wq.x, cpb[2 * i + 0], ab0);
                FFMA2(ab1, wq.y, cpb[2 * i + 1], ab1);
            }
            ull sa; FADD2(sa, aa0, aa1);
            ull sb; FADD2(sb, ab0, ab1);
            float wa0, wa1; UPK2(wa0, wa1, sa);
            float wb0, wb1; UPK2(wb0, wb1, sb);
            float wa = wa0 + wa1;
            float wb = wb0 + wb1;
            float n = qa[u] * wa + qb[u] * wb;
            float cc = wa * wa + wb * wb;
            // start fold: first xor-8 exchange (n<->cc)
            float v = hi8 ? cc : n;
            float o = hi8 ? n : cc;
            vch[u] = v + __shfl_xor_sync(0xffffffffu, o, 8);
        }
        // pipelined tails: 4 independent chains
        #pragma unroll
        for (int u = 0; u < 4; u++) vch[u] += __shfl_xor_sync(0xffffffffu, vch[u], 4);
        #pragma unroll
        for (int u = 0; u < 4; u++) vch[u] += __shfl_xor_sync(0xffffffffu, vch[u], 2);
        #pragma unroll
        for (int u = 0; u < 4; u++) vch[u] += __shfl_xor_sync(0xffffffffu, vch[u], 1);
        if ((gl & 7) == 0) {
            #pragma unroll
            for (int u = 0; u < 4; u++) {
                if (hi8) xc[(l0 + u) * NBLK + kblk] = vch[u];
                else     xn[(l0 + u) * NBLK + kblk] = vch[u];
            }
        }
    }
    __syncthreads();

    // phase 3.5: combine partials -> xs, write g_x (coalesced)
    {
        float* xg = g_x + (size_t)(c * B_IMG + b) * (L_W * NBLK);
        #pragma unroll
        for (int p = t; p < L_W * NBLK; p += 512) {
            int l = p >> 5;
            float den = fmaxf(qsh[p] * sqrtf(xc[p]), 1e-8f);
            float x = (xn[p] / den) * ssc[l];
            xs[p] = x;
            xg[p] = x;
        }
    }
    __syncthreads();

    // phase 4: sim = mean_l( tanh(x @ W1c^T + b1) @ W2 ) + b2
    ull w1p[16];
    #pragma unroll
    for (int j = 0; j < 16; j++)
        w1p[j] = *(const ull*)&g_W1p[j * HID + t];
    float bb1 = b1[t];
    float w2 = W2[t];
    float acc = 0.f;
    #pragma unroll 4
    for (int l = 0; l < L_W; l++) {
        const ulonglong2* x4 = (const ulonglong2*)(xs + l * NBLK);
        ull d2; PK2(d2, bb1, 0.f);
        #pragma unroll
        for (int j = 0; j < 8; j++) {
            ulonglong2 xq = x4[j];
            FFMA2(d2, xq.x, w1p[2 * j + 0], d2);
            FFMA2(d2, xq.y, w1p[2 * j + 1], d2);
        }
        float dlo, dhi; UPK2(dlo, dhi, d2);
        float th; TANH_APX(th, dlo + dhi);
        acc = fmaf(th, w2, acc);
    }
    #pragma unroll
    for (int o = 16; o; o >>= 1) acc += __shfl_down_sync(0xffffffffu, acc, o);
    if (lane == 0) red[warp] = acc;
    __syncthreads();
    if (t == 0) {
        float s = 0.f;
        #pragma unroll
        for (int i = 0; i < 16; i++) s += red[i];
        out_sim[b * C_CAP + c] = s * (1.f / 32.f) + b2[0];
    }
}

// ---------------- kernel D: softmax over captions ----------------
__global__ void k_softmax(const float* __restrict__ sims) {
    int b = blockIdx.x;
    int t = threadIdx.x;  // 64
    __shared__ float sh[64];
    __shared__ float mx, sm;
    float v = sims[b * C_CAP + t];
    sh[t] = v;
    __syncthreads();
    if (t == 0) {
        float m = sh[0];
        for (int i = 1; i < 64; i++) m = fmaxf(m, sh[i]);
        mx = m;
    }
    __syncthreads();
    float e = __expf(v - mx);
    sh[t] = e;
    __syncthreads();
    if (t == 0) {
        float s = 0.f;
        for (int i = 0; i < 64; i++) s += sh[i];
        sm = s;
    }
    __syncthreads();
    g_w[b * C_CAP + t] = e / sm;
}

// ---------------- kernel E: moments via quadratic form (R12 math, isolated retry) ----------------
// var = sum_c w*exp(dl) + wm^T M wm - (xbar.wm)^2 ;  mu = xbar.wm + bm
// where M = sum_c w_c x_c x_c^T, xbar = sum_c w_c x_c  (exact algebra)
__global__ void __launch_bounds__(512) k_moments(const float* __restrict__ bmu,
                                                 const float* __restrict__ blv,
                                                 float* __restrict__ out) {
    int bl = blockIdx.x;        // b*32 + l
    int b = bl >> 5, l = bl & 31;
    int t = threadIdx.x;        // 512 (h)
    __shared__ __align__(16) float xsh[C_CAP * NBLK];
    __shared__ __align__(16) float ysh[C_CAP * NBLK];   // w_c * x
    __shared__ float wsh[C_CAP];
    __shared__ __align__(16) float xbar[NBLK];
    __shared__ __align__(16) float Msh[NBLK * 36];      // stride 36 -> 16B-aligned rows
    for (int i = t; i < C_CAP * NBLK / 4; i += 512) {
        int c = i >> 3, k4 = i & 7;
        ((float4*)xsh)[i] = *(const float4*)(g_x + (size_t)(c * B_IMG + b) * (L_W * NBLK) + l * NBLK + k4 * 4);
    }
    if (t < C_CAP) wsh[t] = g_w[b * C_CAP + t];
    __syncthreads();

    // ysh = w_c * x ; xbar = sum_c w_c x_c
    #pragma unroll
    for (int i = t; i < C_CAP * NBLK; i += 512) ysh[i] = wsh[i >> 5] * xsh[i];
    if (t < NBLK) {
        float s = 0.f;
        #pragma unroll 4
        for (int c = 0; c < C_CAP; c++) s = fmaf(wsh[c], xsh[c * NBLK + t], s);
        xbar[t] = s;
    }
    __syncthreads();

    // M[j][2kp..2kp+1] = sum_c ysh[c][j] * x[c][2kp..2kp+1]
    {
        int j = t >> 4, kp = t & 15;
        ull acc2 = 0ULL;
        #pragma unroll 4
        for (int cc = 0; cc < C_CAP; cc++) {
            float wx = ysh[cc * NBLK + j];
            ull xq = *(const ull*)(xsh + cc * NBLK + 2 * kp);
            ull wx2; PK2(wx2, wx, wx);
            FFMA2(acc2, wx2, xq, acc2);
        }
        float m0, m1; UPK2(m0, m1, acc2);
        Msh[j * 36 + 2 * kp]     = m0;
        Msh[j * 36 + 2 * kp + 1] = m1;
    }
    __syncthreads();

    // per-h (t = h)
    ull wmp[16], wlp[16];
    #pragma unroll
    for (int j = 0; j < 16; j++) {
        wmp[j] = *(const ull*)&g_Wmp[j * HID + t];
        wlp[j] = *(const ull*)&g_Wlp[j * HID + t];
    }
    float bm = bmu[t], bv = blv[t];
    // tdot = xbar . wm
    float tdot;
    {
        ull a2 = 0ULL;
        const ulonglong2* xb = (const ulonglong2*)xbar;
        #pragma unroll
        for (int i = 0; i < 8; i++) {
            ulonglong2 xq = xb[i];
            FFMA2(a2, xq.x, wmp[2 * i], a2);
            FFMA2(a2, xq.y, wmp[2 * i + 1], a2);
        }
        float lo, hi; UPK2(lo, hi, a2);
        tdot = lo + hi;
    }
    // es = sum_c w exp(dl)
    float es = 0.f;
    #pragma unroll 2
    for (int c = 0; c < C_CAP; c++) {
        ull d2; PK2(d2, bv, 0.f);
        const ulonglong2* xr = (const ulonglong2*)(xsh + c * NBLK);
        #pragma unroll
        for (int i = 0; i < 8; i++) {
            ulonglong2 xq = xr[i];
            FFMA2(d2, xq.x, wlp[2 * i], d2);
            FFMA2(d2, xq.y, wlp[2 * i + 1], d2);
        }
        float lo, hi; UPK2(lo, hi, d2);
        es = fmaf(wsh[c], __expf(lo + hi), es);
    }
    // qf = wm^T M wm
    float qf = 0.f;
    #pragma unroll 2
    for (int j = 0; j < NBLK; j++) {
        ull v2 = 0ULL;
        const ulonglong2* mr = (const ulonglong2*)(Msh + j * 36);
        #pragma unroll
        for (int i = 0; i < 8; i++) {
            ulonglong2 mq = mr[i];
            FFMA2(v2, mq.x, wmp[2 * i], v2);
            FFMA2(v2, mq.y, wmp[2 * i + 1], v2);
        }
        float lo, hi; UPK2(lo, hi, v2);
        float w0, w1; UPK2(w0, w1, wmp[j >> 1]);
        float wmj = (j & 1) ? w1 : w0;
        qf = fmaf(wmj, lo + hi, qf);
    }
    float mu = tdot + bm;
    float var = es + qf - tdot * tdot;
    float sg = sqrtf(fmaxf(var, 1e-8f));
    size_t o = (size_t)bl * HID + t;
    out[4096 + o] = mu;
    out[4096 + (size_t)B_IMG * L_W * HID + o] = sg;
}

// ---------------- launch ----------------
extern "C" void kernel_launch(void* const* d_in, const int* in_sizes, int n_in,
                              void* d_out, int out_size) {
    const float* images   = (const float*)d_in[0];
    const float* captions = (const float*)d_in[1];
    const int*   depends  = (const int*)d_in[2];
    const float* W_gc     = (const float*)d_in[3];
    const float* W_mu     = (const float*)d_in[4];
    const float* b_mu     = (const float*)d_in[5];
    const float* W_lv     = (const float*)d_in[6];
    const float* b_lv     = (const float*)d_in[7];
    const float* W1       = (const float*)d_in[8];
    const float* b1       = (const float*)d_in[9];
    const float* W2       = (const float*)d_in[10];
    const float* b2       = (const float*)d_in[11];
    float* out = (float*)d_out;

    static bool init_done = false;
    static cudaStream_t s2;
    static cudaEvent_t evFork, evJoin;
    if (!init_done) {
        cudaFuncSetAttribute(k_caption, cudaFuncAttributeMaxDynamicSharedMemorySize,
                             A_SMEM_FLOATS * sizeof(float));
        cudaStreamCreateWithFlags(&s2, cudaStreamNonBlocking);
        cudaEventCreateWithFlags(&evFork, cudaEventDisableTiming);
        cudaEventCreateWithFlags(&evJoin, cudaEventDisableTiming);
        init_done = true;
    }

    float* attn_ptr;
    cudaGetSymbolAddress((void**)&attn_ptr, g_attn);

    // fork: gemm on s2 in parallel with compose+caption on the main (captured) stream
    cudaEventRecord(evFork, 0);
    cudaStreamWaitEvent(s2, evFork, 0);
    k_gemm_nt<<<dim3(8, 18), 512, 0, s2>>>(images, captions, attn_ptr);
    cudaEventRecord(evJoin, s2);

    k_compose<<<dim3(HID, 3), 32>>>(W_gc, W_mu, W_lv, W1);
    k_caption<<<C_CAP, 256, A_SMEM_FLOATS * sizeof(float)>>>(captions, depends);

    // join before k_fused (needs g_attn + g_scap/g_qns + weights)
    cudaStreamWaitEvent(0, evJoin, 0);

    k_fused<<<dim3(C_CAP, B_IMG), 512>>>(images, captions, b1, W2, b2, out);
    k_softmax<<<B_IMG, 64>>>(out);
    k_moments<<<B_IMG * L_W, 512>>>(b_mu, b_lv, out);
}

// round 15
// speedup vs baseline: 1.1271x; 1.1271x over previous
#include <cuda_runtime.h>
#include <math.h>
#include <stdint.h>

// ---------------- dims ----------------
#define B_IMG 64
#define R_REG 36
#define E_DIM 1024
#define C_CAP 64
#define L_W   32
#define N_DEP 30
#define NBLK  32
#define BLK   32
#define HID   512
#define LAM   9.0f

typedef unsigned long long ull;

// f32x2 packed helpers (sm_100+ PTX)
#define PK2(d, lo, hi)   asm("mov.b64 %0, {%1, %2};" : "=l"(d) : "f"(lo), "f"(hi))
#define UPK2(lo, hi, s)  asm("mov.b64 {%0, %1}, %2;" : "=f"(lo), "=f"(hi) : "l"(s))
#define FFMA2(d, a, b, c) asm("fma.rn.f32x2 %0, %1, %2, %3;" : "=l"(d) : "l"(a), "l"(b), "l"(c))
#define FADD2(d, a, b)    asm("add.rn.f32x2 %0, %1, %2;" : "=l"(d) : "l"(a), "l"(b))
#define TANH_APX(d, a)    asm("tanh.approx.f32 %0, %1;" : "=f"(d) : "f"(a))

// ---------------- scratch ----------------
__device__ float g_attn[(size_t)B_IMG * R_REG * C_CAP * L_W];
__device__ float g_scap[C_CAP * L_W];
__device__ float g_qns[C_CAP * L_W * NBLK];
__device__ float g_x[(size_t)C_CAP * B_IMG * L_W * NBLK];
__device__ float g_w[B_IMG * C_CAP];
__device__ float2 g_Wml[NBLK * HID];            // [k][h] -> (wmu, wlv)
__device__ float2 g_W1p[(NBLK / 2) * HID];      // [k-pair][h] -> (w1[2j], w1[2j+1])

// ---------------- compose W @ W_gc ----------------
__global__ void k_compose(const float* __restrict__ Wgc,
                          const float* __restrict__ Wmu,
                          const float* __restrict__ Wlv,
                          const float* __restrict__ W1) {
    int h = blockIdx.x;
    int m = blockIdx.y;
    int k = threadIdx.x;  // 0..31
    const float* W = (m == 0) ? Wmu : (m == 1) ? Wlv : W1;
    float acc = 0.f;
    #pragma unroll 8
    for (int j = 0; j < HID; j++)
        acc += W[h * HID + j] * Wgc[j * NBLK + k];
    if (m == 0)      g_Wml[k * HID + h].x = acc;
    else if (m == 1) g_Wml[k * HID + h].y = acc;
    else {
        if (k & 1) g_W1p[(k >> 1) * HID + h].y = acc;
        else       g_W1p[(k >> 1) * HID + h].x = acc;
    }
}

// ---------------- kernel A: per-caption s[l] + block norms ----------------
#define A_SMEM_FLOATS (32 * 1025 + 1024 + 1024)
__global__ void k_caption(const float* __restrict__ caps,
                          const int* __restrict__ deps) {
    int c = blockIdx.x;
    int t = threadIdx.x;  // 256
    extern __shared__ float sh[];
    float* cs  = sh;                  // [32][1025]
    float* G   = cs + 32 * 1025;
    float* adj = G + 1024;

    const float* cp = caps + (size_t)c * L_W * E_DIM;
    for (int i = t; i < L_W * E_DIM; i += 256) {
        int l = i >> 10, e = i & 1023;
        cs[l * 1025 + e] = cp[i];
    }
    __syncthreads();

    for (int p = t; p < 1024; p += 256) {
        int l = p >> 5, k = p & 31;
        float s = 0.f;
        #pragma unroll
        for (int j = 0; j < 32; j++) {
            float v = cs[l * 1025 + k * 32 + j];
            s += v * v;
        }
        g_qns[c * 1024 + p] = sqrtf(s);
    }

    for (int p = t; p < 1024; p += 256) {
        int i = p >> 5, j = p & 31;
        float acc = 0.f;
        #pragma unroll 8
        for (int e = 0; e < E_DIM; e++)
            acc += cs[i * 1025 + e] * cs[j * 1025 + e];
        G[p] = acc;
    }
    __syncthreads();

    if (t < 32) {
        float m = -1e30f;
        for (int j = 0; j < 32; j++) m = fmaxf(m, G[t * 32 + j]);
        float s = 0.f;
        for (int j = 0; j < 32; j++) {
            float e = __expf(LAM * (G[t * 32 + j] - m));
            G[t * 32 + j] = e;
            s += e;
        }
        float inv = 1.f / s;
        for (int j = 0; j < 32; j++) G[t * 32 + j] *= inv;
    }
    for (int p = t; p < 1024; p += 256) adj[p] = 0.f;
    __syncthreads();
    if (t == 0) {
        for (int i = 1; i < N_DEP; i++) {
            int a = deps[c * (N_DEP * 2) + i * 2 + 0];
            int b = deps[c * (N_DEP * 2) + i * 2 + 1];
            adj[a * 32 + b] = 1.f;
            adj[b * 32 + a] = 1.f;
        }
        for (int i = 0; i < 32; i++) adj[i * 32 + i] += 1.f;
    }
    __syncthreads();
    if (t < 32) {
        float ss = 0.f;
        for (int j = 0; j < 32; j++) {
            float m2 = adj[t * 32 + j] * G[t * 32 + j];
            ss += m2 * m2;
        }
        float inv = 1.f / (sqrtf(ss) + 1e-8f);
        float s = 0.f;
        for (int j = 0; j < 32; j++) {
            float a = adj[t * 32 + j];
            s += a * G[t * 32 + j] * inv * a;
        }
        g_scap[c * 32 + t] = s;
    }
}

// ---------------- kernel B: logits GEMM, f32x2 packed (R13 proven form) ----------------
__global__ void __launch_bounds__(256) k_gemm_nt(const float* __restrict__ A,
                                                 const float* __restrict__ B,
                                                 float* __restrict__ C) {
    __shared__ __align__(16) float As[2][8][132];
    __shared__ __align__(16) float Bs[2][8][132];
    int tm = blockIdx.y, tn = blockIdx.x;
    int t = threadIdx.x;
    int ty = t >> 4, tx = t & 15;
    int lr = t >> 1;
    int lk = (t & 1) * 4;
    const float* Ab = A + (size_t)(tm * 128 + lr) * E_DIM + lk;
    const float* Bb = B + (size_t)(tn * 128 + lr) * E_DIM + lk;
    ull acc[8][4];
    #pragma unroll
    for (int i = 0; i < 8; i++)
        #pragma unroll
        for (int j = 0; j < 4; j++) acc[i][j] = 0ULL;

    float4 av = *(const float4*)(Ab);
    float4 bv = *(const float4*)(Bb);
    As[0][lk + 0][lr] = av.x; As[0][lk + 1][lr] = av.y;
    As[0][lk + 2][lr] = av.z; As[0][lk + 3][lr] = av.w;
    Bs[0][lk + 0][lr] = bv.x; Bs[0][lk + 1][lr] = bv.y;
    Bs[0][lk + 2][lr] = bv.z; Bs[0][lk + 3][lr] = bv.w;
    __syncthreads();

    int p = 0;
    for (int k0 = 0; k0 < E_DIM; k0 += 8) {
        if (k0 + 8 < E_DIM) {
            av = *(const float4*)(Ab + k0 + 8);
            bv = *(const float4*)(Bb + k0 + 8);
        }
        #pragma unroll
        for (int k = 0; k < 8; k++) {
            float4 a0 = *(const float4*)&As[p][k][ty * 4];
            float4 a1 = *(const float4*)&As[p][k][64 + ty * 4];
            ulonglong2 bq0 = *(const ulonglong2*)&Bs[p][k][tx * 4];
            ulonglong2 bq1 = *(const ulonglong2*)&Bs[p][k][64 + tx * 4];
            float a_[8] = {a0.x, a0.y, a0.z, a0.w, a1.x, a1.y, a1.z, a1.w};
            #pragma unroll
            for (int i = 0; i < 8; i++) {
                ull ai2; PK2(ai2, a_[i], a_[i]);
                FFMA2(acc[i][0], ai2, bq0.x, acc[i][0]);
                FFMA2(acc[i][1], ai2, bq0.y, acc[i][1]);
                FFMA2(acc[i][2], ai2, bq1.x, acc[i][2]);
                FFMA2(acc[i][3], ai2, bq1.y, acc[i][3]);
            }
        }
        if (k0 + 8 < E_DIM) {
            int q = p ^ 1;
            As[q][lk + 0][lr] = av.x; As[q][lk + 1][lr] = av.y;
            As[q][lk + 2][lr] = av.z; As[q][lk + 3][lr] = av.w;
            Bs[q][lk + 0][lr] = bv.x; Bs[q][lk + 1][lr] = bv.y;
            Bs[q][lk + 2][lr] = bv.z; Bs[q][lk + 3][lr] = bv.w;
            __syncthreads();
            p = q;
        }
    }
    const int N = C_CAP * L_W;
    #pragma unroll
    for (int i = 0; i < 8; i++) {
        int row = tm * 128 + ((i < 4) ? (ty * 4 + i) : (64 + ty * 4 + (i - 4)));
        float c0, c1, c2, c3, c4, c5, c6, c7;
        UPK2(c0, c1, acc[i][0]); UPK2(c2, c3, acc[i][1]);
        UPK2(c4, c5, acc[i][2]); UPK2(c6, c7, acc[i][3]);
        *(float4*)(C + (size_t)row * N + tn * 128 + tx * 4) = make_float4(c0, c1, c2, c3);
        *(float4*)(C + (size_t)row * N + tn * 128 + 64 + tx * 4) = make_float4(c4, c5, c6, c7);
    }
}

// ---------------- kernel C: fused per-(c,b) (R13 proven form, UNCHANGED) ----------------
__global__ void __launch_bounds__(512) k_fused(const float* __restrict__ imgs,
                                               const float* __restrict__ caps,
                                               const float* __restrict__ b1,
                                               const float* __restrict__ W2,
                                               const float* __restrict__ b2,
                                               float* __restrict__ out_sim) {
    int c = blockIdx.x;
    int b = blockIdx.y;
    int t = threadIdx.x;  // 512 = 16 warps
    int warp = t >> 5, lane = t & 31;
    __shared__ __align__(16) float tnorm[L_W * 37];
    __shared__ __align__(16) float wlr[L_W * R_REG];  // [l][36]
    __shared__ __align__(16) float xs[L_W * NBLK];
    __shared__ __align__(16) float xn[L_W * NBLK];    // numerator partials
    __shared__ __align__(16) float xc[L_W * NBLK];    // wctx-norm^2 partials
    __shared__ float ssc[L_W];
    __shared__ __align__(16) float qsh[L_W * NBLK];
    __shared__ float red[16];

    for (int i = t; i < 1024; i += 512) qsh[i] = g_qns[c * 1024 + i];
    if (t < L_W) ssc[t] = g_scap[c * L_W + t];

    // phase 1 (coalesced): warp = region, lane = word
    #pragma unroll
    for (int p = 0; p < 3; p++) {
        int r = warp + p * 16;
        if (r < R_REG) {
            float a = g_attn[((size_t)(b * R_REG + r)) * (C_CAP * L_W) + c * L_W + lane];
            a = (a >= 0.f) ? a : 0.1f * a;
            float ss = a * a;
            #pragma unroll
            for (int o = 16; o; o >>= 1) ss += __shfl_xor_sync(0xffffffffu, ss, o);
            tnorm[lane * 37 + r] = a * (1.f / (sqrtf(ss) + 1e-8f));
        }
    }
    __syncthreads();
    // softmax over regions per word
    if (t < L_W) {
        float m = -1e30f;
        #pragma unroll
        for (int r = 0; r < R_REG; r++) m = fmaxf(m, tnorm[t * 37 + r]);
        float s = 0.f;
        float e[R_REG];
        #pragma unroll
        for (int r = 0; r < R_REG; r++) {
            e[r] = __expf(LAM * (tnorm[t * 37 + r] - m));
            s += e[r];
        }
        float inv = 1.f / s;
        #pragma unroll
        for (int r = 0; r < R_REG; r++) wlr[t * R_REG + r] = e[r] * inv;
    }
    __syncthreads();

    // phase 2+3: 16-lane group owns one block; lane gl owns elements gl, gl+16
    int group = lane >> 4;            // 0 or 1
    int gl = lane & 15;
    int kblk = warp + 16 * group;     // block index 0..31
    int ea = kblk * 32 + gl;
    int eb = ea + 16;
    const float* imgb = imgs + (size_t)b * R_REG * E_DIM;
    const float* capc = caps + (size_t)c * L_W * E_DIM;
    ull cpa[18], cpb[18];             // natural-r pairs (img[2i][e], img[2i+1][e])
    #pragma unroll
    for (int i = 0; i < 18; i++) {
        float va0 = imgb[(2 * i) * E_DIM + ea];
        float va1 = imgb[(2 * i + 1) * E_DIM + ea];
        PK2(cpa[i], va0, va1);
        float vb0 = imgb[(2 * i) * E_DIM + eb];
        float vb1 = imgb[(2 * i + 1) * E_DIM + eb];
        PK2(cpb[i], vb0, vb1);
    }
    bool hi8 = (gl & 8) != 0;
    #pragma unroll 1
    for (int l0 = 0; l0 < L_W; l0 += 4) {
        // prefetch the 4 q-pairs
        float qa[4], qb[4];
        #pragma unroll
        for (int u = 0; u < 4; u++) {
            qa[u] = capc[(l0 + u) * E_DIM + ea];
            qb[u] = capc[(l0 + u) * E_DIM + eb];
        }
        float vch[4];
        #pragma unroll
        for (int u = 0; u < 4; u++) {
            const ulonglong2* wp = (const ulonglong2*)(wlr + (l0 + u) * R_REG);
            ull aa0 = 0ULL, aa1 = 0ULL, ab0 = 0ULL, ab1 = 0ULL;
            #pragma unroll
            for (int i = 0; i < 9; i++) {
                ulonglong2 wq = wp[i];
                FFMA2(aa0, wq.x, cpa[2 * i + 0], aa0);
                FFMA2(aa1, wq.y, cpa[2 * i + 1], aa1);
                FFMA2(ab0, wq.x, cpb[2 * i + 0], ab0);
                FFMA2(ab1, wq.y, cpb[2 * i + 1], ab1);
            }
            ull sa; FADD2(sa, aa0, aa1);
            ull sb; FADD2(sb, ab0, ab1);
            float wa0, wa1; UPK2(wa0, wa1, sa);
            float wb0, wb1; UPK2(wb0, wb1, sb);
            float wa = wa0 + wa1;
            float wb = wb0 + wb1;
            float n = qa[u] * wa + qb[u] * wb;
            float cc = wa * wa + wb * wb;
            // start fold: first xor-8 exchange (n<->cc)
            float v = hi8 ? cc : n;
            float o = hi8 ? n : cc;
            vch[u] = v + __shfl_xor_sync(0xffffffffu, o, 8);
        }
        // pipelined tails: 4 independent chains
        #pragma unroll
        for (int u = 0; u < 4; u++) vch[u] += __shfl_xor_sync(0xffffffffu, vch[u], 4);
        #pragma unroll
        for (int u = 0; u < 4; u++) vch[u] += __shfl_xor_sync(0xffffffffu, vch[u], 2);
        #pragma unroll
        for (int u = 0; u < 4; u++) vch[u] += __shfl_xor_sync(0xffffffffu, vch[u], 1);
        if ((gl & 7) == 0) {
            #pragma unroll
            for (int u = 0; u < 4; u++) {
                if (hi8) xc[(l0 + u) * NBLK + kblk] = vch[u];
                else     xn[(l0 + u) * NBLK + kblk] = vch[u];
            }
        }
    }
    __syncthreads();

    // phase 3.5: combine partials -> xs, write g_x (coalesced)
    {
        float* xg = g_x + (size_t)(c * B_IMG + b) * (L_W * NBLK);
        #pragma unroll
        for (int p = t; p < L_W * NBLK; p += 512) {
            int l = p >> 5;
            float den = fmaxf(qsh[p] * sqrtf(xc[p]), 1e-8f);
            float x = (xn[p] / den) * ssc[l];
            xs[p] = x;
            xg[p] = x;
        }
    }
    __syncthreads();

    // phase 4: sim = mean_l( tanh(x @ W1c^T + b1) @ W2 ) + b2
    ull w1p[16];
    #pragma unroll
    for (int j = 0; j < 16; j++)
        w1p[j] = *(const ull*)&g_W1p[j * HID + t];
    float bb1 = b1[t];
    float w2 = W2[t];
    float acc = 0.f;
    #pragma unroll 4
    for (int l = 0; l < L_W; l++) {
        const ulonglong2* x4 = (const ulonglong2*)(xs + l * NBLK);
        ull d2; PK2(d2, bb1, 0.f);
        #pragma unroll
        for (int j = 0; j < 8; j++) {
            ulonglong2 xq = x4[j];
            FFMA2(d2, xq.x, w1p[2 * j + 0], d2);
            FFMA2(d2, xq.y, w1p[2 * j + 1], d2);
        }
        float dlo, dhi; UPK2(dlo, dhi, d2);
        float th; TANH_APX(th, dlo + dhi);
        acc = fmaf(th, w2, acc);
    }
    #pragma unroll
    for (int o = 16; o; o >>= 1) acc += __shfl_down_sync(0xffffffffu, acc, o);
    if (lane == 0) red[warp] = acc;
    __syncthreads();
    if (t == 0) {
        float s = 0.f;
        #pragma unroll
        for (int i = 0; i < 16; i++) s += red[i];
        out_sim[b * C_CAP + c] = s * (1.f / 32.f) + b2[0];
    }
}

// ---------------- kernel D: softmax over captions (shuffle reductions) ----------------
__global__ void k_softmax(const float* __restrict__ sims) {
    int b = blockIdx.x;
    int t = threadIdx.x;  // 64 = 2 warps
    int warp = t >> 5, lane = t & 31;
    __shared__ float wm_[2], ws_[2];
    float v = sims[b * C_CAP + t];
    float m = v;
    #pragma unroll
    for (int o = 16; o; o >>= 1) m = fmaxf(m, __shfl_xor_sync(0xffffffffu, m, o));
    if (lane == 0) wm_[warp] = m;
    __syncthreads();
    float M = fmaxf(wm_[0], wm_[1]);
    float e = __expf(v - M);
    float s = e;
    #pragma unroll
    for (int o = 16; o; o >>= 1) s += __shfl_xor_sync(0xffffffffu, s, o);
    if (lane == 0) ws_[warp] = s;
    __syncthreads();
    float S = ws_[0] + ws_[1];
    g_w[b * C_CAP + t] = e / S;
}

// ---------------- kernel E: weighted Gaussian moments (R11/R13 proven form, unroll 4) ----------------
__global__ void __launch_bounds__(512) k_moments(const float* __restrict__ bmu,
                                                 const float* __restrict__ blv,
                                                 float* __restrict__ out) {
    int bl = blockIdx.x;        // b*32 + l
    int b = bl >> 5, l = bl & 31;
    int t = threadIdx.x;        // 512 (h)
    __shared__ __align__(16) float xsh[C_CAP * NBLK];
    __shared__ float wsh[C_CAP];
    for (int i = t; i < C_CAP * NBLK / 4; i += 512) {
        int c = i >> 3, k4 = i & 7;
        ((float4*)xsh)[i] = *(const float4*)(g_x + (size_t)(c * B_IMG + b) * (L_W * NBLK) + l * NBLK + k4 * 4);
    }
    if (t < C_CAP) wsh[t] = g_w[b * C_CAP + t];
    __syncthreads();

    ull wml[NBLK];
    #pragma unroll
    for (int k = 0; k < NBLK; k++)
        wml[k] = *(const ull*)&g_Wml[k * HID + t];   // (wmu, wlv)
    ull bias2; PK2(bias2, bmu[t], blv[t]);
    float am = 0.f, ae = 0.f;
    #pragma unroll 4
    for (int c = 0; c < C_CAP; c++) {
        const float4* xr4 = (const float4*)(xsh + c * NBLK);
        ull d2 = bias2;
        #pragma unroll
        for (int k4 = 0; k4 < 8; k4++) {
            float4 xv = xr4[k4];
            ull x0, x1, x2, x3;
            PK2(x0, xv.x, xv.x); PK2(x1, xv.y, xv.y);
            PK2(x2, xv.z, xv.z); PK2(x3, xv.w, xv.w);
            FFMA2(d2, x0, wml[k4 * 4 + 0], d2);
            FFMA2(d2, x1, wml[k4 * 4 + 1], d2);
            FFMA2(d2, x2, wml[k4 * 4 + 2], d2);
            FFMA2(d2, x3, wml[k4 * 4 + 3], d2);
        }
        float dm, dl; UPK2(dm, dl, d2);
        float w = wsh[c];
        am = fmaf(w, dm, am);
        ae = fmaf(w, __expf(dl) + dm * dm, ae);
    }
    float var = ae - am * am;
    float sg = sqrtf(fmaxf(var, 1e-8f));
    size_t o = (size_t)bl * HID + t;
    out[4096 + o] = am;
    out[4096 + (size_t)B_IMG * L_W * HID + o] = sg;
}

// ---------------- launch ----------------
extern "C" void kernel_launch(void* const* d_in, const int* in_sizes, int n_in,
                              void* d_out, int out_size) {
    const float* images   = (const float*)d_in[0];
    const float* captions = (const float*)d_in[1];
    const int*   depends  = (const int*)d_in[2];
    const float* W_gc     = (const float*)d_in[3];
    const float* W_mu     = (const float*)d_in[4];
    const float* b_mu     = (const float*)d_in[5];
    const float* W_lv     = (const float*)d_in[6];
    const float* b_lv     = (const float*)d_in[7];
    const float* W1       = (const float*)d_in[8];
    const float* b1       = (const float*)d_in[9];
    const float* W2       = (const float*)d_in[10];
    const float* b2       = (const float*)d_in[11];
    float* out = (float*)d_out;

    static bool init_done = false;
    static cudaStream_t s2;
    static cudaEvent_t evFork, evJoin;
    if (!init_done) {
        cudaFuncSetAttribute(k_caption, cudaFuncAttributeMaxDynamicSharedMemorySize,
                             A_SMEM_FLOATS * sizeof(float));
        cudaStreamCreateWithFlags(&s2, cudaStreamNonBlocking);
        cudaEventCreateWithFlags(&evFork, cudaEventDisableTiming);
        cudaEventCreateWithFlags(&evJoin, cudaEventDisableTiming);
        init_done = true;
    }

    float* attn_ptr;
    cudaGetSymbolAddress((void**)&attn_ptr, g_attn);

    // fork: gemm on s2 in parallel with compose+caption on the main (captured) stream
    cudaEventRecord(evFork, 0);
    cudaStreamWaitEvent(s2, evFork, 0);
    k_gemm_nt<<<dim3(16, 18), 256, 0, s2>>>(images, captions, attn_ptr);
    cudaEventRecord(evJoin, s2);

    k_compose<<<dim3(HID, 3), 32>>>(W_gc, W_mu, W_lv, W1);
    k_caption<<<C_CAP, 256, A_SMEM_FLOATS * sizeof(float)>>>(captions, depends);

    // join before k_fused (needs g_attn + g_scap/g_qns + weights)
    cudaStreamWaitEvent(0, evJoin, 0);

    k_fused<<<dim3(C_CAP, B_IMG), 512>>>(images, captions, b1, W2, b2, out);
    k_softmax<<<B_IMG, 64>>>(out);
    k_moments<<<B_IMG * L_W, 512>>>(b_mu, b_lv, out);
}

// round 16
// speedup vs baseline: 1.2107x; 1.0742x over previous
#include <cuda_runtime.h>
#include <math.h>
#include <stdint.h>

// ---------------- dims ----------------
#define B_IMG 64
#define R_REG 36
#define E_DIM 1024
#define C_CAP 64
#define L_W   32
#define N_DEP 30
#define NBLK  32
#define BLK   32
#define HID   512
#define LAM   9.0f

typedef unsigned long long ull;

// f32x2 packed helpers (sm_100+ PTX)
#define PK2(d, lo, hi)   asm("mov.b64 %0, {%1, %2};" : "=l"(d) : "f"(lo), "f"(hi))
#define UPK2(lo, hi, s)  asm("mov.b64 {%0, %1}, %2;" : "=f"(lo), "=f"(hi) : "l"(s))
#define FFMA2(d, a, b, c) asm("fma.rn.f32x2 %0, %1, %2, %3;" : "=l"(d) : "l"(a), "l"(b), "l"(c))
#define FADD2(d, a, b)    asm("add.rn.f32x2 %0, %1, %2;" : "=l"(d) : "l"(a), "l"(b))
#define TANH_APX(d, a)    asm("tanh.approx.f32 %0, %1;" : "=f"(d) : "f"(a))

// ---------------- scratch ----------------
__device__ float g_attn[(size_t)B_IMG * R_REG * C_CAP * L_W];
__device__ float g_scap[C_CAP * L_W];
__device__ float g_qns[C_CAP * L_W * NBLK];
__device__ float g_wlr[(size_t)B_IMG * C_CAP * L_W * R_REG];  // [b][c*32+l][36]
__device__ float g_xn[(size_t)C_CAP * B_IMG * L_W * NBLK];    // block numerators
__device__ float g_xc[(size_t)C_CAP * B_IMG * L_W * NBLK];    // block wctx norms^2
__device__ float g_x[(size_t)C_CAP * B_IMG * L_W * NBLK];
__device__ float g_w[B_IMG * C_CAP];
__device__ float2 g_Wml[NBLK * HID];            // [k][h] -> (wmu, wlv)
__device__ float2 g_W1p[(NBLK / 2) * HID];      // [k-pair][h] -> (w1[2j], w1[2j+1])

// ---------------- compose W @ W_gc ----------------
__global__ void k_compose(const float* __restrict__ Wgc,
                          const float* __restrict__ Wmu,
                          const float* __restrict__ Wlv,
                          const float* __restrict__ W1) {
    int h = blockIdx.x;
    int m = blockIdx.y;
    int k = threadIdx.x;  // 0..31
    const float* W = (m == 0) ? Wmu : (m == 1) ? Wlv : W1;
    float acc = 0.f;
    #pragma unroll 8
    for (int j = 0; j < HID; j++)
        acc += W[h * HID + j] * Wgc[j * NBLK + k];
    if (m == 0)      g_Wml[k * HID + h].x = acc;
    else if (m == 1) g_Wml[k * HID + h].y = acc;
    else {
        if (k & 1) g_W1p[(k >> 1) * HID + h].y = acc;
        else       g_W1p[(k >> 1) * HID + h].x = acc;
    }
}

// ---------------- kernel A: per-caption s[l] + block norms (proven) ----------------
#define A_SMEM_FLOATS (32 * 1025 + 1024 + 1024)
__global__ void k_caption(const float* __restrict__ caps,
                          const int* __restrict__ deps) {
    int c = blockIdx.x;
    int t = threadIdx.x;  // 256
    extern __shared__ float sh[];
    float* cs  = sh;                  // [32][1025]
    float* G   = cs + 32 * 1025;
    float* adj = G + 1024;

    const float* cp = caps + (size_t)c * L_W * E_DIM;
    for (int i = t; i < L_W * E_DIM; i += 256) {
        int l = i >> 10, e = i & 1023;
        cs[l * 1025 + e] = cp[i];
    }
    __syncthreads();

    for (int p = t; p < 1024; p += 256) {
        int l = p >> 5, k = p & 31;
        float s = 0.f;
        #pragma unroll
        for (int j = 0; j < 32; j++) {
            float v = cs[l * 1025 + k * 32 + j];
            s += v * v;
        }
        g_qns[c * 1024 + p] = sqrtf(s);
    }

    for (int p = t; p < 1024; p += 256) {
        int i = p >> 5, j = p & 31;
        float acc = 0.f;
        #pragma unroll 8
        for (int e = 0; e < E_DIM; e++)
            acc += cs[i * 1025 + e] * cs[j * 1025 + e];
        G[p] = acc;
    }
    __syncthreads();

    if (t < 32) {
        float m = -1e30f;
        for (int j = 0; j < 32; j++) m = fmaxf(m, G[t * 32 + j]);
        float s = 0.f;
        for (int j = 0; j < 32; j++) {
            float e = __expf(LAM * (G[t * 32 + j] - m));
            G[t * 32 + j] = e;
            s += e;
        }
        float inv = 1.f / s;
        for (int j = 0; j < 32; j++) G[t * 32 + j] *= inv;
    }
    for (int p = t; p < 1024; p += 256) adj[p] = 0.f;
    __syncthreads();
    if (t == 0) {
        for (int i = 1; i < N_DEP; i++) {
            int a = deps[c * (N_DEP * 2) + i * 2 + 0];
            int b = deps[c * (N_DEP * 2) + i * 2 + 1];
            adj[a * 32 + b] = 1.f;
            adj[b * 32 + a] = 1.f;
        }
        for (int i = 0; i < 32; i++) adj[i * 32 + i] += 1.f;
    }
    __syncthreads();
    if (t < 32) {
        float ss = 0.f;
        for (int j = 0; j < 32; j++) {
            float m2 = adj[t * 32 + j] * G[t * 32 + j];
            ss += m2 * m2;
        }
        float inv = 1.f / (sqrtf(ss) + 1e-8f);
        float s = 0.f;
        for (int j = 0; j < 32; j++) {
            float a = adj[t * 32 + j];
            s += a * G[t * 32 + j] * inv * a;
        }
        g_scap[c * 32 + t] = s;
    }
}

// ---------------- kernel B: logits GEMM (proven) ----------------
__global__ void __launch_bounds__(256) k_gemm_nt(const float* __restrict__ A,
                                                 const float* __restrict__ B,
                                                 float* __restrict__ C) {
    __shared__ __align__(16) float As[2][8][132];
    __shared__ __align__(16) float Bs[2][8][132];
    int tm = blockIdx.y, tn = blockIdx.x;
    int t = threadIdx.x;
    int ty = t >> 4, tx = t & 15;
    int lr = t >> 1;
    int lk = (t & 1) * 4;
    const float* Ab = A + (size_t)(tm * 128 + lr) * E_DIM + lk;
    const float* Bb = B + (size_t)(tn * 128 + lr) * E_DIM + lk;
    ull acc[8][4];
    #pragma unroll
    for (int i = 0; i < 8; i++)
        #pragma unroll
        for (int j = 0; j < 4; j++) acc[i][j] = 0ULL;

    float4 av = *(const float4*)(Ab);
    float4 bv = *(const float4*)(Bb);
    As[0][lk + 0][lr] = av.x; As[0][lk + 1][lr] = av.y;
    As[0][lk + 2][lr] = av.z; As[0][lk + 3][lr] = av.w;
    Bs[0][lk + 0][lr] = bv.x; Bs[0][lk + 1][lr] = bv.y;
    Bs[0][lk + 2][lr] = bv.z; Bs[0][lk + 3][lr] = bv.w;
    __syncthreads();

    int p = 0;
    for (int k0 = 0; k0 < E_DIM; k0 += 8) {
        if (k0 + 8 < E_DIM) {
            av = *(const float4*)(Ab + k0 + 8);
            bv = *(const float4*)(Bb + k0 + 8);
        }
        #pragma unroll
        for (int k = 0; k < 8; k++) {
            float4 a0 = *(const float4*)&As[p][k][ty * 4];
            float4 a1 = *(const float4*)&As[p][k][64 + ty * 4];
            ulonglong2 bq0 = *(const ulonglong2*)&Bs[p][k][tx * 4];
            ulonglong2 bq1 = *(const ulonglong2*)&Bs[p][k][64 + tx * 4];
            float a_[8] = {a0.x, a0.y, a0.z, a0.w, a1.x, a1.y, a1.z, a1.w};
            #pragma unroll
            for (int i = 0; i < 8; i++) {
                ull ai2; PK2(ai2, a_[i], a_[i]);
                FFMA2(acc[i][0], ai2, bq0.x, acc[i][0]);
                FFMA2(acc[i][1], ai2, bq0.y, acc[i][1]);
                FFMA2(acc[i][2], ai2, bq1.x, acc[i][2]);
                FFMA2(acc[i][3], ai2, bq1.y, acc[i][3]);
            }
        }
        if (k0 + 8 < E_DIM) {
            int q = p ^ 1;
            As[q][lk + 0][lr] = av.x; As[q][lk + 1][lr] = av.y;
            As[q][lk + 2][lr] = av.z; As[q][lk + 3][lr] = av.w;
            Bs[q][lk + 0][lr] = bv.x; Bs[q][lk + 1][lr] = bv.y;
            Bs[q][lk + 2][lr] = bv.z; Bs[q][lk + 3][lr] = bv.w;
            __syncthreads();
            p = q;
        }
    }
    const int N = C_CAP * L_W;
    #pragma unroll
    for (int i = 0; i < 8; i++) {
        int row = tm * 128 + ((i < 4) ? (ty * 4 + i) : (64 + ty * 4 + (i - 4)));
        float c0, c1, c2, c3, c4, c5, c6, c7;
        UPK2(c0, c1, acc[i][0]); UPK2(c2, c3, acc[i][1]);
        UPK2(c4, c5, acc[i][2]); UPK2(c6, c7, acc[i][3]);
        *(float4*)(C + (size_t)row * N + tn * 128 + tx * 4) = make_float4(c0, c1, c2, c3);
        *(float4*)(C + (size_t)row * N + tn * 128 + 64 + tx * 4) = make_float4(c4, c5, c6, c7);
    }
}

// ---------------- kernel W: attention weights wlr (from k_fused phase 1) ----------------
__global__ void __launch_bounds__(512) k_wlr(void) {
    int c = blockIdx.x;
    int b = blockIdx.y;
    int t = threadIdx.x;  // 512 = 16 warps
    int warp = t >> 5, lane = t & 31;
    __shared__ __align__(16) float tnorm[L_W * 37];

    #pragma unroll
    for (int p = 0; p < 3; p++) {
        int r = warp + p * 16;
        if (r < R_REG) {
            float a = g_attn[((size_t)(b * R_REG + r)) * (C_CAP * L_W) + c * L_W + lane];
            a = (a >= 0.f) ? a : 0.1f * a;
            float ss = a * a;
            #pragma unroll
            for (int o = 16; o; o >>= 1) ss += __shfl_xor_sync(0xffffffffu, ss, o);
            tnorm[lane * 37 + r] = a * (1.f / (sqrtf(ss) + 1e-8f));
        }
    }
    __syncthreads();
    if (t < L_W) {
        float m = -1e30f;
        #pragma unroll
        for (int r = 0; r < R_REG; r++) m = fmaxf(m, tnorm[t * 37 + r]);
        float s = 0.f;
        float e[R_REG];
        #pragma unroll
        for (int r = 0; r < R_REG; r++) {
            e[r] = __expf(LAM * (tnorm[t * 37 + r] - m));
            s += e[r];
        }
        float inv = 1.f / s;
        float* wout = g_wlr + ((size_t)b * (C_CAP * L_W) + c * L_W + t) * R_REG;
        #pragma unroll
        for (int r = 0; r < R_REG; r++) wout[r] = e[r] * inv;
    }
}

// ---------------- kernel G: wctx GEMM + block-cosine epilogue ----------------
// per b: W_all(2048 x 36) @ imgb(36 x 1024); tile 128x128, K=36 one-shot
__global__ void __launch_bounds__(256) k_wgemm(const float* __restrict__ imgs,
                                               const float* __restrict__ caps) {
    __shared__ __align__(16) float As[R_REG][132];   // [k][row]
    __shared__ __align__(16) float Bs[R_REG][132];   // [k][e]
    int ntile = blockIdx.x;   // 0..7
    int mtile = blockIdx.y;   // 0..15
    int b = blockIdx.z;       // 0..63
    int t = threadIdx.x;      // 256
    int ty = t >> 4, tx = t & 15;
    int lane = t & 31;

    // load A tile: g_wlr rows [mtile*128, +128), 36 k each; transpose into As[k][row]
    {
        const float* Aall = g_wlr + ((size_t)b * (C_CAP * L_W) + mtile * 128) * R_REG;
        #pragma unroll
        for (int i = t; i < 128 * R_REG; i += 256) {
            int row = i / R_REG, k = i - row * R_REG;
            As[k][row] = Aall[i];
        }
    }
    // load B tile: imgs[b][k][ntile*128 + e]
    {
        const float* Bb = imgs + (size_t)b * R_REG * E_DIM + ntile * 128;
        #pragma unroll
        for (int i = t; i < R_REG * 128; i += 256) {
            int k = i >> 7, e = i & 127;
            Bs[k][e] = Bb[k * E_DIM + e];
        }
    }
    __syncthreads();

    ull acc[8][4];
    #pragma unroll
    for (int i = 0; i < 8; i++)
        #pragma unroll
        for (int j = 0; j < 4; j++) acc[i][j] = 0ULL;

    #pragma unroll
    for (int k = 0; k < R_REG; k++) {
        float4 a0 = *(const float4*)&As[k][ty * 4];
        float4 a1 = *(const float4*)&As[k][64 + ty * 4];
        ulonglong2 bq0 = *(const ulonglong2*)&Bs[k][tx * 4];
        ulonglong2 bq1 = *(const ulonglong2*)&Bs[k][64 + tx * 4];
        float a_[8] = {a0.x, a0.y, a0.z, a0.w, a1.x, a1.y, a1.z, a1.w};
        #pragma unroll
        for (int i = 0; i < 8; i++) {
            ull ai2; PK2(ai2, a_[i], a_[i]);
            FFMA2(acc[i][0], ai2, bq0.x, acc[i][0]);
            FFMA2(acc[i][1], ai2, bq0.y, acc[i][1]);
            FFMA2(acc[i][2], ai2, bq1.x, acc[i][2]);
            FFMA2(acc[i][3], ai2, bq1.y, acc[i][3]);
        }
    }

    // epilogue: per (row, 32-col block) n = sum q*w, cc = sum w*w
    #pragma unroll
    for (int i = 0; i < 8; i++) {
        int r_loc = (i < 4) ? (ty * 4 + i) : (64 + ty * 4 + (i - 4));
        int row = mtile * 128 + r_loc;            // = c*32 + l
        const float* qp = caps + (size_t)row * E_DIM + ntile * 128;
        #pragma unroll
        for (int g = 0; g < 2; g++) {
            float w0, w1, w2, w3;
            UPK2(w0, w1, acc[i][2 * g]);
            UPK2(w2, w3, acc[i][2 * g + 1]);
            float4 q4 = *(const float4*)(qp + g * 64 + tx * 4);
            float np = q4.x * w0 + q4.y * w1 + q4.z * w2 + q4.w * w3;
            float cp = w0 * w0 + w1 * w1 + w2 * w2 + w3 * w3;
            bool hi4 = (lane & 4) != 0;
            float v = hi4 ? cp : np;
            float o = hi4 ? np : cp;
            v += __shfl_xor_sync(0xffffffffu, o, 4);
            v += __shfl_xor_sync(0xffffffffu, v, 2);
            v += __shfl_xor_sync(0xffffffffu, v, 1);
            int blk = ntile * 4 + g * 2 + (tx >> 3);
            size_t oidx = ((size_t)(row >> 5) * B_IMG + b) * (L_W * NBLK) + (row & 31) * NBLK + blk;
            if ((lane & 7) == 0) g_xn[oidx] = v;
            else if ((lane & 7) == 4) g_xc[oidx] = v;
        }
    }
}

// ---------------- kernel C2: combine + sim head ----------------
__global__ void __launch_bounds__(512, 2) k_sim(const float* __restrict__ b1,
                                                const float* __restrict__ W2,
                                                const float* __restrict__ b2,
                                                float* __restrict__ out_sim) {
    int c = blockIdx.x;
    int b = blockIdx.y;
    int t = threadIdx.x;  // 512 (h)
    int warp = t >> 5, lane = t & 31;
    __shared__ __align__(16) float xs[L_W * NBLK];
    __shared__ float red[16];
    if (t < 256) {
        size_t base = (size_t)(c * B_IMG + b) * (L_W * NBLK) + t * 4;
        float4 n4 = *(const float4*)(g_xn + base);
        float4 c4 = *(const float4*)(g_xc + base);
        float4 q4 = *(const float4*)(g_qns + c * 1024 + t * 4);
        float sc = g_scap[c * L_W + (t >> 3)];
        float4 x;
        x.x = n4.x / fmaxf(q4.x * sqrtf(c4.x), 1e-8f) * sc;
        x.y = n4.y / fmaxf(q4.y * sqrtf(c4.y), 1e-8f) * sc;
        x.z = n4.z / fmaxf(q4.z * sqrtf(c4.z), 1e-8f) * sc;
        x.w = n4.w / fmaxf(q4.w * sqrtf(c4.w), 1e-8f) * sc;
        ((float4*)xs)[t] = x;
        *(float4*)(g_x + base) = x;
    }
    __syncthreads();

    ull w1p[16];
    #pragma unroll
    for (int j = 0; j < 16; j++)
        w1p[j] = *(const ull*)&g_W1p[j * HID + t];
    float bb1 = b1[t];
    float w2 = W2[t];
    float acc = 0.f;
    #pragma unroll 4
    for (int l = 0; l < L_W; l++) {
        const ulonglong2* x4 = (const ulonglong2*)(xs + l * NBLK);
        ull d2; PK2(d2, bb1, 0.f);
        #pragma unroll
        for (int j = 0; j < 8; j++) {
            ulonglong2 xq = x4[j];
            FFMA2(d2, xq.x, w1p[2 * j + 0], d2);
            FFMA2(d2, xq.y, w1p[2 * j + 1], d2);
        }
        float dlo, dhi; UPK2(dlo, dhi, d2);
        float th; TANH_APX(th, dlo + dhi);
        acc = fmaf(th, w2, acc);
    }
    #pragma unroll
    for (int o = 16; o; o >>= 1) acc += __shfl_down_sync(0xffffffffu, acc, o);
    if (lane == 0) red[warp] = acc;
    __syncthreads();
    if (t == 0) {
        float s = 0.f;
        #pragma unroll
        for (int i = 0; i < 16; i++) s += red[i];
        out_sim[b * C_CAP + c] = s * (1.f / 32.f) + b2[0];
    }
}

// ---------------- kernel D: softmax over captions (proven) ----------------
__global__ void k_softmax(const float* __restrict__ sims) {
    int b = blockIdx.x;
    int t = threadIdx.x;  // 64 = 2 warps
    int warp = t >> 5, lane = t & 31;
    __shared__ float wm_[2], ws_[2];
    float v = sims[b * C_CAP + t];
    float m = v;
    #pragma unroll
    for (int o = 16; o; o >>= 1) m = fmaxf(m, __shfl_xor_sync(0xffffffffu, m, o));
    if (lane == 0) wm_[warp] = m;
    __syncthreads();
    float M = fmaxf(wm_[0], wm_[1]);
    float e = __expf(v - M);
    float s = e;
    #pragma unroll
    for (int o = 16; o; o >>= 1) s += __shfl_xor_sync(0xffffffffu, s, o);
    if (lane == 0) ws_[warp] = s;
    __syncthreads();
    float S = ws_[0] + ws_[1];
    g_w[b * C_CAP + t] = e / S;
}

// ---------------- kernel E: weighted Gaussian moments (proven) ----------------
__global__ void __launch_bounds__(512) k_moments(const float* __restrict__ bmu,
                                                 const float* __restrict__ blv,
                                                 float* __restrict__ out) {
    int bl = blockIdx.x;        // b*32 + l
    int b = bl >> 5, l = bl & 31;
    int t = threadIdx.x;        // 512 (h)
    __shared__ __align__(16) float xsh[C_CAP * NBLK];
    __shared__ float wsh[C_CAP];
    for (int i = t; i < C_CAP * NBLK / 4; i += 512) {
        int c = i >> 3, k4 = i & 7;
        ((float4*)xsh)[i] = *(const float4*)(g_x + (size_t)(c * B_IMG + b) * (L_W * NBLK) + l * NBLK + k4 * 4);
    }
    if (t < C_CAP) wsh[t] = g_w[b * C_CAP + t];
    __syncthreads();

    ull wml[NBLK];
    #pragma unroll
    for (int k = 0; k < NBLK; k++)
        wml[k] = *(const ull*)&g_Wml[k * HID + t];   // (wmu, wlv)
    ull bias2; PK2(bias2, bmu[t], blv[t]);
    float am = 0.f, ae = 0.f;
    #pragma unroll 4
    for (int c = 0; c < C_CAP; c++) {
        const float4* xr4 = (const float4*)(xsh + c * NBLK);
        ull d2 = bias2;
        #pragma unroll
        for (int k4 = 0; k4 < 8; k4++) {
            float4 xv = xr4[k4];
            ull x0, x1, x2, x3;
            PK2(x0, xv.x, xv.x); PK2(x1, xv.y, xv.y);
            PK2(x2, xv.z, xv.z); PK2(x3, xv.w, xv.w);
            FFMA2(d2, x0, wml[k4 * 4 + 0], d2);
            FFMA2(d2, x1, wml[k4 * 4 + 1], d2);
            FFMA2(d2, x2, wml[k4 * 4 + 2], d2);
            FFMA2(d2, x3, wml[k4 * 4 + 3], d2);
        }
        float dm, dl; UPK2(dm, dl, d2);
        float w = wsh[c];
        am = fmaf(w, dm, am);
        ae = fmaf(w, __expf(dl) + dm * dm, ae);
    }
    float var = ae - am * am;
    float sg = sqrtf(fmaxf(var, 1e-8f));
    size_t o = (size_t)bl * HID + t;
    out[4096 + o] = am;
    out[4096 + (size_t)B_IMG * L_W * HID + o] = sg;
}

// ---------------- launch ----------------
extern "C" void kernel_launch(void* const* d_in, const int* in_sizes, int n_in,
                              void* d_out, int out_size) {
    const float* images   = (const float*)d_in[0];
    const float* captions = (const float*)d_in[1];
    const int*   depends  = (const int*)d_in[2];
    const float* W_gc     = (const float*)d_in[3];
    const float* W_mu     = (const float*)d_in[4];
    const float* b_mu     = (const float*)d_in[5];
    const float* W_lv     = (const float*)d_in[6];
    const float* b_lv     = (const float*)d_in[7];
    const float* W1       = (const float*)d_in[8];
    const float* b1       = (const float*)d_in[9];
    const float* W2       = (const float*)d_in[10];
    const float* b2       = (const float*)d_in[11];
    float* out = (float*)d_out;

    static bool init_done = false;
    static cudaStream_t s2;
    static cudaEvent_t evFork, evJoin;
    if (!init_done) {
        cudaFuncSetAttribute(k_caption, cudaFuncAttributeMaxDynamicSharedMemorySize,
                             A_SMEM_FLOATS * sizeof(float));
        cudaStreamCreateWithFlags(&s2, cudaStreamNonBlocking);
        cudaEventCreateWithFlags(&evFork, cudaEventDisableTiming);
        cudaEventCreateWithFlags(&evJoin, cudaEventDisableTiming);
        init_done = true;
    }

    float* attn_ptr;
    cudaGetSymbolAddress((void**)&attn_ptr, g_attn);

    // fork: logits gemm + wlr on s2, compose+caption on main stream
    cudaEventRecord(evFork, 0);
    cudaStreamWaitEvent(s2, evFork, 0);
    k_gemm_nt<<<dim3(16, 18), 256, 0, s2>>>(images, captions, attn_ptr);
    k_wlr<<<dim3(C_CAP, B_IMG), 512, 0, s2>>>();
    cudaEventRecord(evJoin, s2);

    k_compose<<<dim3(HID, 3), 32>>>(W_gc, W_mu, W_lv, W1);
    k_caption<<<C_CAP, 256, A_SMEM_FLOATS * sizeof(float)>>>(captions, depends);

    cudaStreamWaitEvent(0, evJoin, 0);

    // wctx GEMM + block-cosine epilogue
    k_wgemm<<<dim3(8, 16, B_IMG), 256>>>(images, captions);
    // combine + sim
    k_sim<<<dim3(C_CAP, B_IMG), 512>>>(b1, W2, b2, out);
    k_softmax<<<B_IMG, 64>>>(out);
    k_moments<<<B_IMG * L_W, 512>>>(b_mu, b_lv, out);
}

// round 17
// speedup vs baseline: 1.2368x; 1.0216x over previous
#include <cuda_runtime.h>
#include <math.h>
#include <stdint.h>

// ---------------- dims ----------------
#define B_IMG 64
#define R_REG 36
#define E_DIM 1024
#define C_CAP 64
#define L_W   32
#define N_DEP 30
#define NBLK  32
#define BLK   32
#define HID   512
#define LAM   9.0f

typedef unsigned long long ull;

// f32x2 packed helpers (sm_100+ PTX)
#define PK2(d, lo, hi)   asm("mov.b64 %0, {%1, %2};" : "=l"(d) : "f"(lo), "f"(hi))
#define UPK2(lo, hi, s)  asm("mov.b64 {%0, %1}, %2;" : "=f"(lo), "=f"(hi) : "l"(s))
#define FFMA2(d, a, b, c) asm("fma.rn.f32x2 %0, %1, %2, %3;" : "=l"(d) : "l"(a), "l"(b), "l"(c))
#define FADD2(d, a, b)    asm("add.rn.f32x2 %0, %1, %2;" : "=l"(d) : "l"(a), "l"(b))
#define TANH_APX(d, a)    asm("tanh.approx.f32 %0, %1;" : "=f"(d) : "f"(a))

// ---------------- scratch ----------------
__device__ float g_attn[(size_t)B_IMG * R_REG * C_CAP * L_W];
__device__ float g_scap[C_CAP * L_W];
__device__ float g_qns[C_CAP * L_W * NBLK];
__device__ float g_wlr[(size_t)B_IMG * R_REG * C_CAP * L_W];  // TRANSPOSED [b][r][c*32+l]
__device__ float g_xn[(size_t)C_CAP * B_IMG * L_W * NBLK];    // block numerators
__device__ float g_xc[(size_t)C_CAP * B_IMG * L_W * NBLK];    // block wctx norms^2
__device__ float g_x[(size_t)C_CAP * B_IMG * L_W * NBLK];
__device__ float g_w[B_IMG * C_CAP];
__device__ float2 g_Wml[NBLK * HID];            // [k][h] -> (wmu, wlv)
__device__ float2 g_W1p[(NBLK / 2) * HID];      // [k-pair][h] -> (w1[2j], w1[2j+1])

// ---------------- compose W @ W_gc ----------------
__global__ void k_compose(const float* __restrict__ Wgc,
                          const float* __restrict__ Wmu,
                          const float* __restrict__ Wlv,
                          const float* __restrict__ W1) {
    int h = blockIdx.x;
    int m = blockIdx.y;
    int k = threadIdx.x;  // 0..31
    const float* W = (m == 0) ? Wmu : (m == 1) ? Wlv : W1;
    float acc = 0.f;
    #pragma unroll 8
    for (int j = 0; j < HID; j++)
        acc += W[h * HID + j] * Wgc[j * NBLK + k];
    if (m == 0)      g_Wml[k * HID + h].x = acc;
    else if (m == 1) g_Wml[k * HID + h].y = acc;
    else {
        if (k & 1) g_W1p[(k >> 1) * HID + h].y = acc;
        else       g_W1p[(k >> 1) * HID + h].x = acc;
    }
}

// ---------------- kernel A: per-caption s[l] + block norms (proven) ----------------
#define A_SMEM_FLOATS (32 * 1025 + 1024 + 1024)
__global__ void k_caption(const float* __restrict__ caps,
                          const int* __restrict__ deps) {
    int c = blockIdx.x;
    int t = threadIdx.x;  // 256
    extern __shared__ float sh[];
    float* cs  = sh;                  // [32][1025]
    float* G   = cs + 32 * 1025;
    float* adj = G + 1024;

    const float* cp = caps + (size_t)c * L_W * E_DIM;
    for (int i = t; i < L_W * E_DIM; i += 256) {
        int l = i >> 10, e = i & 1023;
        cs[l * 1025 + e] = cp[i];
    }
    __syncthreads();

    for (int p = t; p < 1024; p += 256) {
        int l = p >> 5, k = p & 31;
        float s = 0.f;
        #pragma unroll
        for (int j = 0; j < 32; j++) {
            float v = cs[l * 1025 + k * 32 + j];
            s += v * v;
        }
        g_qns[c * 1024 + p] = sqrtf(s);
    }

    for (int p = t; p < 1024; p += 256) {
        int i = p >> 5, j = p & 31;
        float acc = 0.f;
        #pragma unroll 8
        for (int e = 0; e < E_DIM; e++)
            acc += cs[i * 1025 + e] * cs[j * 1025 + e];
        G[p] = acc;
    }
    __syncthreads();

    if (t < 32) {
        float m = -1e30f;
        for (int j = 0; j < 32; j++) m = fmaxf(m, G[t * 32 + j]);
        float s = 0.f;
        for (int j = 0; j < 32; j++) {
            float e = __expf(LAM * (G[t * 32 + j] - m));
            G[t * 32 + j] = e;
            s += e;
        }
        float inv = 1.f / s;
        for (int j = 0; j < 32; j++) G[t * 32 + j] *= inv;
    }
    for (int p = t; p < 1024; p += 256) adj[p] = 0.f;
    __syncthreads();
    if (t == 0) {
        for (int i = 1; i < N_DEP; i++) {
            int a = deps[c * (N_DEP * 2) + i * 2 + 0];
            int b = deps[c * (N_DEP * 2) + i * 2 + 1];
            adj[a * 32 + b] = 1.f;
            adj[b * 32 + a] = 1.f;
        }
        for (int i = 0; i < 32; i++) adj[i * 32 + i] += 1.f;
    }
    __syncthreads();
    if (t < 32) {
        float ss = 0.f;
        for (int j = 0; j < 32; j++) {
            float m2 = adj[t * 32 + j] * G[t * 32 + j];
            ss += m2 * m2;
        }
        float inv = 1.f / (sqrtf(ss) + 1e-8f);
        float s = 0.f;
        for (int j = 0; j < 32; j++) {
            float a = adj[t * 32 + j];
            s += a * G[t * 32 + j] * inv * a;
        }
        g_scap[c * 32 + t] = s;
    }
}

// ---------------- kernel B: logits GEMM (proven) ----------------
__global__ void __launch_bounds__(256) k_gemm_nt(const float* __restrict__ A,
                                                 const float* __restrict__ B,
                                                 float* __restrict__ C) {
    __shared__ __align__(16) float As[2][8][132];
    __shared__ __align__(16) float Bs[2][8][132];
    int tm = blockIdx.y, tn = blockIdx.x;
    int t = threadIdx.x;
    int ty = t >> 4, tx = t & 15;
    int lr = t >> 1;
    int lk = (t & 1) * 4;
    const float* Ab = A + (size_t)(tm * 128 + lr) * E_DIM + lk;
    const float* Bb = B + (size_t)(tn * 128 + lr) * E_DIM + lk;
    ull acc[8][4];
    #pragma unroll
    for (int i = 0; i < 8; i++)
        #pragma unroll
        for (int j = 0; j < 4; j++) acc[i][j] = 0ULL;

    float4 av = *(const float4*)(Ab);
    float4 bv = *(const float4*)(Bb);
    As[0][lk + 0][lr] = av.x; As[0][lk + 1][lr] = av.y;
    As[0][lk + 2][lr] = av.z; As[0][lk + 3][lr] = av.w;
    Bs[0][lk + 0][lr] = bv.x; Bs[0][lk + 1][lr] = bv.y;
    Bs[0][lk + 2][lr] = bv.z; Bs[0][lk + 3][lr] = bv.w;
    __syncthreads();

    int p = 0;
    for (int k0 = 0; k0 < E_DIM; k0 += 8) {
        if (k0 + 8 < E_DIM) {
            av = *(const float4*)(Ab + k0 + 8);
            bv = *(const float4*)(Bb + k0 + 8);
        }
        #pragma unroll
        for (int k = 0; k < 8; k++) {
            float4 a0 = *(const float4*)&As[p][k][ty * 4];
            float4 a1 = *(const float4*)&As[p][k][64 + ty * 4];
            ulonglong2 bq0 = *(const ulonglong2*)&Bs[p][k][tx * 4];
            ulonglong2 bq1 = *(const ulonglong2*)&Bs[p][k][64 + tx * 4];
            float a_[8] = {a0.x, a0.y, a0.z, a0.w, a1.x, a1.y, a1.z, a1.w};
            #pragma unroll
            for (int i = 0; i < 8; i++) {
                ull ai2; PK2(ai2, a_[i], a_[i]);
                FFMA2(acc[i][0], ai2, bq0.x, acc[i][0]);
                FFMA2(acc[i][1], ai2, bq0.y, acc[i][1]);
                FFMA2(acc[i][2], ai2, bq1.x, acc[i][2]);
                FFMA2(acc[i][3], ai2, bq1.y, acc[i][3]);
            }
        }
        if (k0 + 8 < E_DIM) {
            int q = p ^ 1;
            As[q][lk + 0][lr] = av.x; As[q][lk + 1][lr] = av.y;
            As[q][lk + 2][lr] = av.z; As[q][lk + 3][lr] = av.w;
            Bs[q][lk + 0][lr] = bv.x; Bs[q][lk + 1][lr] = bv.y;
            Bs[q][lk + 2][lr] = bv.z; Bs[q][lk + 3][lr] = bv.w;
            __syncthreads();
            p = q;
        }
    }
    const int N = C_CAP * L_W;
    #pragma unroll
    for (int i = 0; i < 8; i++) {
        int row = tm * 128 + ((i < 4) ? (ty * 4 + i) : (64 + ty * 4 + (i - 4)));
        float c0, c1, c2, c3, c4, c5, c6, c7;
        UPK2(c0, c1, acc[i][0]); UPK2(c2, c3, acc[i][1]);
        UPK2(c4, c5, acc[i][2]); UPK2(c6, c7, acc[i][3]);
        *(float4*)(C + (size_t)row * N + tn * 128 + tx * 4) = make_float4(c0, c1, c2, c3);
        *(float4*)(C + (size_t)row * N + tn * 128 + 64 + tx * 4) = make_float4(c4, c5, c6, c7);
    }
}

// ---------------- kernel W: attention weights wlr (transposed output) ----------------
__global__ void __launch_bounds__(512) k_wlr(void) {
    int c = blockIdx.x;
    int b = blockIdx.y;
    int t = threadIdx.x;  // 512 = 16 warps
    int warp = t >> 5, lane = t & 31;
    __shared__ __align__(16) float tnorm[L_W * 37];

    #pragma unroll
    for (int p = 0; p < 3; p++) {
        int r = warp + p * 16;
        if (r < R_REG) {
            float a = g_attn[((size_t)(b * R_REG + r)) * (C_CAP * L_W) + c * L_W + lane];
            a = (a >= 0.f) ? a : 0.1f * a;
            float ss = a * a;
            #pragma unroll
            for (int o = 16; o; o >>= 1) ss += __shfl_xor_sync(0xffffffffu, ss, o);
            tnorm[lane * 37 + r] = a * (1.f / (sqrtf(ss) + 1e-8f));
        }
    }
    __syncthreads();
    if (t < L_W) {
        float m = -1e30f;
        #pragma unroll
        for (int r = 0; r < R_REG; r++) m = fmaxf(m, tnorm[t * 37 + r]);
        float s = 0.f;
        float e[R_REG];
        #pragma unroll
        for (int r = 0; r < R_REG; r++) {
            e[r] = __expf(LAM * (tnorm[t * 37 + r] - m));
            s += e[r];
        }
        float inv = 1.f / s;
        // transposed: g_wlr[b][r][c*32 + l] -- coalesced over l per r
        float* wout = g_wlr + (size_t)b * (R_REG * C_CAP * L_W) + c * L_W + t;
        #pragma unroll
        for (int r = 0; r < R_REG; r++) wout[(size_t)r * (C_CAP * L_W)] = e[r] * inv;
    }
}

// ---------------- kernel G: wctx GEMM + block-cosine epilogue (float4 tile loads) ----------------
__global__ void __launch_bounds__(256) k_wgemm(const float* __restrict__ imgs,
                                               const float* __restrict__ caps) {
    __shared__ __align__(16) float As[R_REG][132];   // [k][row]
    __shared__ __align__(16) float Bs[R_REG][132];   // [k][e]
    int ntile = blockIdx.x;   // 0..7
    int mtile = blockIdx.y;   // 0..15
    int b = blockIdx.z;       // 0..63
    int t = threadIdx.x;      // 256
    int ty = t >> 4, tx = t & 15;
    int lane = t & 31;

    // A tile: g_wlr[b][k][mtile*128 + row], rows contiguous -> float4 copy
    {
        const float* Aall = g_wlr + (size_t)b * (R_REG * C_CAP * L_W) + mtile * 128;
        #pragma unroll
        for (int i = t; i < R_REG * 32; i += 256) {
            int k = i >> 5, r4 = i & 31;
            *(float4*)&As[k][r4 * 4] = *(const float4*)(Aall + (size_t)k * (C_CAP * L_W) + r4 * 4);
        }
    }
    // B tile: imgs[b][k][ntile*128 + e] -> float4 copy
    {
        const float* Bb = imgs + (size_t)b * R_REG * E_DIM + ntile * 128;
        #pragma unroll
        for (int i = t; i < R_REG * 32; i += 256) {
            int k = i >> 5, e4 = i & 31;
            *(float4*)&Bs[k][e4 * 4] = *(const float4*)(Bb + k * E_DIM + e4 * 4);
        }
    }
    __syncthreads();

    ull acc[8][4];
    #pragma unroll
    for (int i = 0; i < 8; i++)
        #pragma unroll
        for (int j = 0; j < 4; j++) acc[i][j] = 0ULL;

    #pragma unroll
    for (int k = 0; k < R_REG; k++) {
        float4 a0 = *(const float4*)&As[k][ty * 4];
        float4 a1 = *(const float4*)&As[k][64 + ty * 4];
        ulonglong2 bq0 = *(const ulonglong2*)&Bs[k][tx * 4];
        ulonglong2 bq1 = *(const ulonglong2*)&Bs[k][64 + tx * 4];
        float a_[8] = {a0.x, a0.y, a0.z, a0.w, a1.x, a1.y, a1.z, a1.w};
        #pragma unroll
        for (int i = 0; i < 8; i++) {
            ull ai2; PK2(ai2, a_[i], a_[i]);
            FFMA2(acc[i][0], ai2, bq0.x, acc[i][0]);
            FFMA2(acc[i][1], ai2, bq0.y, acc[i][1]);
            FFMA2(acc[i][2], ai2, bq1.x, acc[i][2]);
            FFMA2(acc[i][3], ai2, bq1.y, acc[i][3]);
        }
    }

    // epilogue: per (row, 32-col block) n = sum q*w, cc = sum w*w
    #pragma unroll
    for (int i = 0; i < 8; i++) {
        int r_loc = (i < 4) ? (ty * 4 + i) : (64 + ty * 4 + (i - 4));
        int row = mtile * 128 + r_loc;            // = c*32 + l
        const float* qp = caps + (size_t)row * E_DIM + ntile * 128;
        #pragma unroll
        for (int g = 0; g < 2; g++) {
            float w0, w1, w2, w3;
            UPK2(w0, w1, acc[i][2 * g]);
            UPK2(w2, w3, acc[i][2 * g + 1]);
            float4 q4 = *(const float4*)(qp + g * 64 + tx * 4);
            float np = q4.x * w0 + q4.y * w1 + q4.z * w2 + q4.w * w3;
            float cp = w0 * w0 + w1 * w1 + w2 * w2 + w3 * w3;
            bool hi4 = (lane & 4) != 0;
            float v = hi4 ? cp : np;
            float o = hi4 ? np : cp;
            v += __shfl_xor_sync(0xffffffffu, o, 4);
            v += __shfl_xor_sync(0xffffffffu, v, 2);
            v += __shfl_xor_sync(0xffffffffu, v, 1);
            int blk = ntile * 4 + g * 2 + (tx >> 3);
            size_t oidx = ((size_t)(row >> 5) * B_IMG + b) * (L_W * NBLK) + (row & 31) * NBLK + blk;
            if ((lane & 7) == 0) g_xn[oidx] = v;
            else if ((lane & 7) == 4) g_xc[oidx] = v;
        }
    }
}

// ---------------- kernel C2: combine + sim head (proven) ----------------
__global__ void __launch_bounds__(512, 2) k_sim(const float* __restrict__ b1,
                                                const float* __restrict__ W2,
                                                const float* __restrict__ b2,
                                                float* __restrict__ out_sim) {
    int c = blockIdx.x;
    int b = blockIdx.y;
    int t = threadIdx.x;  // 512 (h)
    int warp = t >> 5, lane = t & 31;
    __shared__ __align__(16) float xs[L_W * NBLK];
    __shared__ float red[16];
    if (t < 256) {
        size_t base = (size_t)(c * B_IMG + b) * (L_W * NBLK) + t * 4;
        float4 n4 = *(const float4*)(g_xn + base);
        float4 c4 = *(const float4*)(g_xc + base);
        float4 q4 = *(const float4*)(g_qns + c * 1024 + t * 4);
        float sc = g_scap[c * L_W + (t >> 3)];
        float4 x;
        x.x = n4.x / fmaxf(q4.x * sqrtf(c4.x), 1e-8f) * sc;
        x.y = n4.y / fmaxf(q4.y * sqrtf(c4.y), 1e-8f) * sc;
        x.z = n4.z / fmaxf(q4.z * sqrtf(c4.z), 1e-8f) * sc;
        x.w = n4.w / fmaxf(q4.w * sqrtf(c4.w), 1e-8f) * sc;
        ((float4*)xs)[t] = x;
        *(float4*)(g_x + base) = x;
    }
    __syncthreads();

    ull w1p[16];
    #pragma unroll
    for (int j = 0; j < 16; j++)
        w1p[j] = *(const ull*)&g_W1p[j * HID + t];
    float bb1 = b1[t];
    float w2 = W2[t];
    float acc = 0.f;
    #pragma unroll 4
    for (int l = 0; l < L_W; l++) {
        const ulonglong2* x4 = (const ulonglong2*)(xs + l * NBLK);
        ull d2; PK2(d2, bb1, 0.f);
        #pragma unroll
        for (int j = 0; j < 8; j++) {
            ulonglong2 xq = x4[j];
            FFMA2(d2, xq.x, w1p[2 * j + 0], d2);
            FFMA2(d2, xq.y, w1p[2 * j + 1], d2);
        }
        float dlo, dhi; UPK2(dlo, dhi, d2);
        float th; TANH_APX(th, dlo + dhi);
        acc = fmaf(th, w2, acc);
    }
    #pragma unroll
    for (int o = 16; o; o >>= 1) acc += __shfl_down_sync(0xffffffffu, acc, o);
    if (lane == 0) red[warp] = acc;
    __syncthreads();
    if (t == 0) {
        float s = 0.f;
        #pragma unroll
        for (int i = 0; i < 16; i++) s += red[i];
        out_sim[b * C_CAP + c] = s * (1.f / 32.f) + b2[0];
    }
}

// ---------------- kernel D: softmax over captions (proven) ----------------
__global__ void k_softmax(const float* __restrict__ sims) {
    int b = blockIdx.x;
    int t = threadIdx.x;  // 64 = 2 warps
    int warp = t >> 5, lane = t & 31;
    __shared__ float wm_[2], ws_[2];
    float v = sims[b * C_CAP + t];
    float m = v;
    #pragma unroll
    for (int o = 16; o; o >>= 1) m = fmaxf(m, __shfl_xor_sync(0xffffffffu, m, o));
    if (lane == 0) wm_[warp] = m;
    __syncthreads();
    float M = fmaxf(wm_[0], wm_[1]);
    float e = __expf(v - M);
    float s = e;
    #pragma unroll
    for (int o = 16; o; o >>= 1) s += __shfl_xor_sync(0xffffffffu, s, o);
    if (lane == 0) ws_[warp] = s;
    __syncthreads();
    float S = ws_[0] + ws_[1];
    g_w[b * C_CAP + t] = e / S;
}

// ---------------- kernel E: weighted Gaussian moments (proven) ----------------
__global__ void __launch_bounds__(512) k_moments(const float* __restrict__ bmu,
                                                 const float* __restrict__ blv,
                                                 float* __restrict__ out) {
    int bl = blockIdx.x;        // b*32 + l
    int b = bl >> 5, l = bl & 31;
    int t = threadIdx.x;        // 512 (h)
    __shared__ __align__(16) float xsh[C_CAP * NBLK];
    __shared__ float wsh[C_CAP];
    for (int i = t; i < C_CAP * NBLK / 4; i += 512) {
        int c = i >> 3, k4 = i & 7;
        ((float4*)xsh)[i] = *(const float4*)(g_x + (size_t)(c * B_IMG + b) * (L_W * NBLK) + l * NBLK + k4 * 4);
    }
    if (t < C_CAP) wsh[t] = g_w[b * C_CAP + t];
    __syncthreads();

    ull wml[NBLK];
    #pragma unroll
    for (int k = 0; k < NBLK; k++)
        wml[k] = *(const ull*)&g_Wml[k * HID + t];   // (wmu, wlv)
    ull bias2; PK2(bias2, bmu[t], blv[t]);
    float am = 0.f, ae = 0.f;
    #pragma unroll 4
    for (int c = 0; c < C_CAP; c++) {
        const float4* xr4 = (const float4*)(xsh + c * NBLK);
        ull d2 = bias2;
        #pragma unroll
        for (int k4 = 0; k4 < 8; k4++) {
            float4 xv = xr4[k4];
            ull x0, x1, x2, x3;
            PK2(x0, xv.x, xv.x); PK2(x1, xv.y, xv.y);
            PK2(x2, xv.z, xv.z); PK2(x3, xv.w, xv.w);
            FFMA2(d2, x0, wml[k4 * 4 + 0], d2);
            FFMA2(d2, x1, wml[k4 * 4 + 1], d2);
            FFMA2(d2, x2, wml[k4 * 4 + 2], d2);
            FFMA2(d2, x3, wml[k4 * 4 + 3], d2);
        }
        float dm, dl; UPK2(dm, dl, d2);
        float w = wsh[c];
        am = fmaf(w, dm, am);
        ae = fmaf(w, __expf(dl) + dm * dm, ae);
    }
    float var = ae - am * am;
    float sg = sqrtf(fmaxf(var, 1e-8f));
    size_t o = (size_t)bl * HID + t;
    out[4096 + o] = am;
    out[4096 + (size_t)B_IMG * L_W * HID + o] = sg;
}

// ---------------- launch ----------------
extern "C" void kernel_launch(void* const* d_in, const int* in_sizes, int n_in,
                              void* d_out, int out_size) {
    const float* images   = (const float*)d_in[0];
    const float* captions = (const float*)d_in[1];
    const int*   depends  = (const int*)d_in[2];
    const float* W_gc     = (const float*)d_in[3];
    const float* W_mu     = (const float*)d_in[4];
    const float* b_mu     = (const float*)d_in[5];
    const float* W_lv     = (const float*)d_in[6];
    const float* b_lv     = (const float*)d_in[7];
    const float* W1       = (const float*)d_in[8];
    const float* b1       = (const float*)d_in[9];
    const float* W2       = (const float*)d_in[10];
    const float* b2       = (const float*)d_in[11];
    float* out = (float*)d_out;

    static bool init_done = false;
    static cudaStream_t s2;
    static cudaEvent_t evFork, evJoin;
    if (!init_done) {
        cudaFuncSetAttribute(k_caption, cudaFuncAttributeMaxDynamicSharedMemorySize,
                             A_SMEM_FLOATS * sizeof(float));
        cudaStreamCreateWithFlags(&s2, cudaStreamNonBlocking);
        cudaEventCreateWithFlags(&evFork, cudaEventDisableTiming);
        cudaEventCreateWithFlags(&evJoin, cudaEventDisableTiming);
        init_done = true;
    }

    float* attn_ptr;
    cudaGetSymbolAddress((void**)&attn_ptr, g_attn);

    // fork: logits gemm + wlr on s2, compose+caption on main stream
    cudaEventRecord(evFork, 0);
    cudaStreamWaitEvent(s2, evFork, 0);
    k_gemm_nt<<<dim3(16, 18), 256, 0, s2>>>(images, captions, attn_ptr);
    k_wlr<<<dim3(C_CAP, B_IMG), 512, 0, s2>>>();
    cudaEventRecord(evJoin, s2);

    k_compose<<<dim3(HID, 3), 32>>>(W_gc, W_mu, W_lv, W1);
    k_caption<<<C_CAP, 256, A_SMEM_FLOATS * sizeof(float)>>>(captions, depends);

    cudaStreamWaitEvent(0, evJoin, 0);

    // wctx GEMM + block-cosine epilogue
    k_wgemm<<<dim3(8, 16, B_IMG), 256>>>(images, captions);
    // combine + sim
    k_sim<<<dim3(C_CAP, B_IMG), 512>>>(b1, W2, b2, out);
    k_softmax<<<B_IMG, 64>>>(out);
    k_moments<<<B_IMG * L_W, 512>>>(b_mu, b_lv, out);
}